// round 9
// baseline (speedup 1.0000x reference)
#include <cuda_runtime.h>
#include <cuda_fp16.h>

// ---------------- problem-size constants (fixed by the dataset) -------------
#define N_MAX   100032      // >= 100000 nodes
#define E_PAD   2001600     // E + 4*N padding headroom
#define D       50          // attrs
#define STRH    64          // padded row stride of fp16 buffers (64 halves = 128B)
#define NITER   30
#define SCAN_B  256

// ---------------- packed f32x2 helpers (sm_103a) -----------------------------
__device__ __forceinline__ unsigned long long h2_to_f32x2(unsigned int h2bits) {
    unsigned long long r;
    asm("{\n\t"
        ".reg .b16 lo, hi;\n\t"
        ".reg .f32 flo, fhi;\n\t"
        "mov.b32 {lo, hi}, %1;\n\t"
        "cvt.f32.f16 flo, lo;\n\t"
        "cvt.f32.f16 fhi, hi;\n\t"
        "mov.b64 %0, {flo, fhi};\n\t"
        "}" : "=l"(r) : "r"(h2bits));
    return r;
}
__device__ __forceinline__ unsigned long long add_f32x2(unsigned long long a,
                                                        unsigned long long b) {
    unsigned long long r;
    asm("add.rn.f32x2 %0, %1, %2;" : "=l"(r) : "l"(a), "l"(b));
    return r;
}
__device__ __forceinline__ float2 unpack_f32x2(unsigned long long p) {
    float2 f;
    asm("mov.b64 {%0, %1}, %2;" : "=f"(f.x), "=f"(f.y) : "l"(p));
    return f;
}

// ---------------- static device scratch (no allocations allowed) ------------
// Invariants at call entry (static zero on load; restored by each call):
//   g_deg == 0 (zeroed in k_iter t==0), g_meansum == 0 and g_ctr == 0
//   (zeroed in k_iter t==NITER-1). g_colsum zeroed inside k_scan_params.
__device__ int    g_deg[N_MAX];
__device__ int2   g_span[N_MAX];         // {start, end} per node (one 8B load)
__device__ int    g_cursor[N_MAX];
__device__ int    g_partial[512];
__device__ int    g_ctr;                 // grid-barrier arrival counter
__device__ int    g_csr[E_PAD];          // col*STRH (half offset); dummies -> row n
__device__ float  g_dinv[N_MAX];
__device__ unsigned char g_isknown[N_MAX];   // idempotent sets; never cleared
__device__ float  g_meansum[64];
__device__ float  g_mean[64];            // pads [50,64) stay 0 forever
__device__ float  g_alpha[64];
__device__ float  g_oma[64];
__device__ float  g_beta[64];
__device__ float  g_omb[64];
__device__ float  g_colsum[(NITER + 1) * 64];
__device__ int    g_need_colmean;        // set iff any alpha != 1
__device__ int    g_need_beta;
// zero-initialized; rows >= n are NEVER written, so dummy gathers read 0.
__device__ __half g_bufA[(size_t)N_MAX * STRH];
__device__ __half g_bufB[(size_t)N_MAX * STRH];

// ---------------- kernel 1: degrees + isknown + mean partials ---------------
__global__ void k_deg_known_mean(const int* __restrict__ row,
                                 const int* __restrict__ km,
                                 const float* __restrict__ x, int E, int K) {
    int i = blockIdx.x * blockDim.x + threadIdx.x;
    if (i < E) atomicAdd(&g_deg[row[i]], 1);
    if (i < K) g_isknown[km[i]] = 1;
    if (blockIdx.x < 100) {
        __shared__ float sm[64];
        if (threadIdx.x < 64) sm[threadIdx.x] = 0.f;
        __syncthreads();
        int lane = threadIdx.x & 31;
        int w  = (blockIdx.x * blockDim.x + threadIdx.x) >> 5;
        int nw = (100 * blockDim.x) >> 5;
        float2 acc = make_float2(0.f, 0.f);
        for (int k = w; k < K; k += nw) {
            int idx = km[k];
            if (lane < 25) {
                float2 vv = *(const float2*)(x + (size_t)idx * D + 2 * lane);
                acc.x += vv.x; acc.y += vv.y;
            }
        }
        if (lane < 25) {
            atomicAdd(&sm[2 * lane],     acc.x);
            atomicAdd(&sm[2 * lane + 1], acc.y);
        }
        __syncthreads();
        if (threadIdx.x < D) atomicAdd(&g_meansum[threadIdx.x], sm[threadIdx.x]);
    }
}

// ---------------- kernel 2: fused scan + spans + params (grid barrier) ------
// grid = ceil(n/256) = 391 blocks — fits in one resident wave; spin is safe.
__global__ void k_scan_params(int n, const float* __restrict__ eta,
                              const float* __restrict__ theta, int K) {
    __shared__ int s[SCAN_B];
    __shared__ int red[SCAN_B];
    __shared__ int fc, fb;
    int b = blockIdx.x, t = threadIdx.x;
    int i = b * SCAN_B + t;
    int nb = gridDim.x;

    if (i < (NITER + 1) * 64) g_colsum[i] = 0.f;

    int dg = (i < n) ? g_deg[i] : 0;
    if (i < n) g_dinv[i] = (dg > 0) ? rsqrtf((float)dg) : 0.f;
    int v = (dg + 3) & ~3;                      // padded length
    s[t] = v;
    __syncthreads();
    for (int d = 1; d < SCAN_B; d <<= 1) {
        int tmp = (t >= d) ? s[t - d] : 0;
        __syncthreads();
        s[t] += tmp;
        __syncthreads();
    }
    int excl = s[t] - v;
    if (t == SCAN_B - 1) {
        g_partial[b] = s[SCAN_B - 1];
        __threadfence();
    }
    __syncthreads();

    if (b == 0) {
        if (t == 0) { fc = 0; fb = 0; }
        __syncthreads();
        if (t < D) {
            g_mean[t] = g_meansum[t] / (float)K;
            float nf = (float)n;
            float a  = (nf - 1.f) / (theta[t] * nf + (nf - 1.f));
            float ia = 1.f / a;
            float bb = ia / (ia + eta[t]);
            g_alpha[t] = a;  g_oma[t] = 1.f - a;
            g_beta[t]  = bb; g_omb[t] = 1.f - bb;
            if (a  != 1.f) atomicExch(&fc, 1);
            if (bb != 1.f) atomicExch(&fb, 1);
        }
        __syncthreads();
        if (t == 0) { g_need_colmean = fc; g_need_beta = fb; }
    }

    // grid barrier: wait for all block totals
    if (t == 0) {
        atomicAdd(&g_ctr, 1);
        while (*(volatile int*)&g_ctr < nb) { }
    }
    __syncthreads();
    __threadfence();

    int local = 0;
    for (int j = t; j < b; j += SCAN_B) local += g_partial[j];
    red[t] = local;
    __syncthreads();
    for (int off = SCAN_B / 2; off > 0; off >>= 1) {
        if (t < off) red[t] += red[t + off];
        __syncthreads();
    }
    int base = red[0];

    if (i < n) {
        int s0 = base + excl;
        g_span[i]   = make_int2(s0, s0 + v);
        g_cursor[i] = s0;
    }
}

// ---------------- kernel 3: fused scatter + pad-fill + y0 init --------------
__global__ void k_build_init(const int* __restrict__ row, const int* __restrict__ col,
                             const float* __restrict__ x, int n, int E) {
    int tidg = blockIdx.x * blockDim.x + threadIdx.x;

    if (tidg < E) {
        int r = row[tidg];
        int p = atomicAdd(&g_cursor[r], 1);
        g_csr[p] = col[tidg] * STRH;
    }

    if (tidg < n) {
        int2 sp = g_span[tidg];
        int dummy = n * STRH;
        for (int j = sp.x + g_deg[tidg]; j < sp.y; ++j) g_csr[j] = dummy;
    }

    int gw   = tidg >> 5;
    int lane = threadIdx.x & 31;
    __shared__ float cs[64];
    int needc = g_need_colmean;
    if (needc) { if (threadIdx.x < 64) cs[threadIdx.x] = 0.f; __syncthreads(); }
    float2 v = make_float2(0.f, 0.f);
    if (gw < n) {
        if (lane < 25 && g_isknown[gw])
            v = *(const float2*)(x + (size_t)gw * D + 2 * lane);
        float2 m = ((const float2*)g_mean)[lane];
        v.x -= m.x; v.y -= m.y;
        float di = g_dinv[gw];
        if (lane < 25)
            *(__half2*)(g_bufA + (size_t)gw * STRH + 2 * lane) =
                __floats2half2_rn(di * v.x, di * v.y);
    }
    if (needc) {
        if (gw < n && lane < 25) {
            atomicAdd(&cs[2 * lane],     v.x);
            atomicAdd(&cs[2 * lane + 1], v.y);
        }
        __syncthreads();
        if (threadIdx.x < D) atomicAdd(&g_colsum[threadIdx.x], cs[threadIdx.x]);
    }
}

// ---------------- the hot loop: one propagation step ------------------------
// warp-per-node; lanes 0..24 own a float2 of the 50 attrs. fp16 gathers,
// converts to fp32, packed add.rn.f32x2 accumulation (full fp32 precision,
// half the add instructions). Two chains hide the 4-cyc ALU latency.
__global__ __launch_bounds__(256) void k_iter(const float* __restrict__ x,
                                              float* __restrict__ fout,
                                              int n, float invn, int t, int last) {
    int tidg = blockIdx.x * blockDim.x + threadIdx.x;
    int gw   = tidg >> 5;
    int lane = threadIdx.x & 31;
    __shared__ float cs[64];
    const int needc = g_need_colmean;
    if (needc) { if (threadIdx.x < 64) cs[threadIdx.x] = 0.f; __syncthreads(); }

    // epilogue/prologue zeroing for the NEXT call (readers all in the past)
    if (t == 0 && tidg < n) g_deg[tidg] = 0;
    if (last) {
        if (tidg < 64) g_meansum[tidg] = 0.f;
        if (tidg == 0) g_ctr = 0;
    }

    const __half* in  = (t & 1) ? g_bufB : g_bufA;
    __half*       out = (t & 1) ? g_bufA : g_bufB;
    const float* cs_in  = g_colsum + t * 64;
    float*       cs_out = g_colsum + (t + 1) * 64;

    float2 v = make_float2(0.f, 0.f);
    if (gw < n) {
        int2 sp = g_span[gw];                     // one 8B uniform load
        int s = sp.x, e = sp.y;                   // 16B aligned, mult of 4
        const __half* inp = in + 2 * lane;
        unsigned long long acc0 = 0ull, acc1 = 0ull;   // packed {0f, 0f}
        int i = s;
        for (; i + 8 <= e; i += 8) {
            int4 c0 = *(const int4*)(g_csr + i);
            int4 c1 = *(const int4*)(g_csr + i + 4);
            unsigned int h0 = *(const unsigned int*)(inp + c0.x);
            unsigned int h1 = *(const unsigned int*)(inp + c0.y);
            unsigned int h2 = *(const unsigned int*)(inp + c0.z);
            unsigned int h3 = *(const unsigned int*)(inp + c0.w);
            unsigned int h4 = *(const unsigned int*)(inp + c1.x);
            unsigned int h5 = *(const unsigned int*)(inp + c1.y);
            unsigned int h6 = *(const unsigned int*)(inp + c1.z);
            unsigned int h7 = *(const unsigned int*)(inp + c1.w);
            acc0 = add_f32x2(acc0, h2_to_f32x2(h0));
            acc1 = add_f32x2(acc1, h2_to_f32x2(h1));
            acc0 = add_f32x2(acc0, h2_to_f32x2(h2));
            acc1 = add_f32x2(acc1, h2_to_f32x2(h3));
            acc0 = add_f32x2(acc0, h2_to_f32x2(h4));
            acc1 = add_f32x2(acc1, h2_to_f32x2(h5));
            acc0 = add_f32x2(acc0, h2_to_f32x2(h6));
            acc1 = add_f32x2(acc1, h2_to_f32x2(h7));
        }
        for (; i < e; i += 4) {
            int4 c0 = *(const int4*)(g_csr + i);
            unsigned int h0 = *(const unsigned int*)(inp + c0.x);
            unsigned int h1 = *(const unsigned int*)(inp + c0.y);
            unsigned int h2 = *(const unsigned int*)(inp + c0.z);
            unsigned int h3 = *(const unsigned int*)(inp + c0.w);
            acc0 = add_f32x2(acc0, h2_to_f32x2(h0));
            acc1 = add_f32x2(acc1, h2_to_f32x2(h1));
            acc0 = add_f32x2(acc0, h2_to_f32x2(h2));
            acc1 = add_f32x2(acc1, h2_to_f32x2(h3));
        }
        float2 acc = unpack_f32x2(add_f32x2(acc0, acc1));
        float di = g_dinv[gw];
        if (needc) {
            float2 a  = ((const float2*)g_alpha)[lane];
            float2 om = ((const float2*)g_oma)[lane];
            v.x = fmaf(a.x, di * acc.x, om.x * (cs_in[2 * lane]     * invn));
            v.y = fmaf(a.y, di * acc.y, om.y * (cs_in[2 * lane + 1] * invn));
        } else {
            v.x = di * acc.x;                     // alpha == 1 exactly
            v.y = di * acc.y;
        }
        if (g_need_beta && g_isknown[gw]) {
            float2 b  = ((const float2*)g_beta)[lane];
            float2 ob = ((const float2*)g_omb)[lane];
            float2 m  = ((const float2*)g_mean)[lane];
            float2 xv = make_float2(0.f, 0.f);
            if (lane < 25) xv = *(const float2*)(x + (size_t)gw * D + 2 * lane);
            v.x = b.x * v.x + ob.x * (xv.x - m.x);
            v.y = b.y * v.y + ob.y * (xv.y - m.y);
        }
        if (last) {
            float2 m = ((const float2*)g_mean)[lane];
            if (lane < 25)
                *(float2*)(fout + (size_t)gw * D + 2 * lane) =
                    make_float2(v.x + m.x, v.y + m.y);
        } else {
            if (lane < 25)
                *(__half2*)(out + (size_t)gw * STRH + 2 * lane) =
                    __floats2half2_rn(di * v.x, di * v.y);
        }
    }
    if (needc && !last) {
        if (gw < n && lane < 25) {
            atomicAdd(&cs[2 * lane],     v.x);
            atomicAdd(&cs[2 * lane + 1], v.y);
        }
        __syncthreads();
        if (threadIdx.x < D) atomicAdd(&cs_out[threadIdx.x], cs[threadIdx.x]);
    }
}

// ---------------- launcher ---------------------------------------------------
extern "C" void kernel_launch(void* const* d_in, const int* in_sizes, int n_in,
                              void* d_out, int out_size) {
    const float* x     = (const float*)d_in[0];
    const float* eta   = (const float*)d_in[1];
    const float* theta = (const float*)d_in[2];
    const int*   ei    = (const int*)d_in[3];
    const int*   km    = (const int*)d_in[4];

    int dd = in_sizes[1];              // 50
    int n  = in_sizes[0] / dd;         // 100000
    int E  = in_sizes[3] / 2;          // 1600000
    int K  = in_sizes[4];              // 50000
    const int* row = ei;
    const int* col = ei + E;

    const int TB = 256;
    int nbN = (n + TB - 1) / TB;       // 391 — one resident wave (safe to spin)
    int nbE = (E + TB - 1) / TB;
    int nbW = (n * 32 + TB - 1) / TB;  // warp-per-node grids (>= E threads)

    k_deg_known_mean<<<nbE, TB>>>(row, km, x, E, K);
    k_scan_params   <<<nbN, TB>>>(n, eta, theta, K);
    k_build_init    <<<nbW, TB>>>(row, col, x, n, E);

    float invn = 1.f / (float)n;
    for (int t = 0; t < NITER; ++t) {
        k_iter<<<nbW, TB>>>(x, (float*)d_out, n, invn, t, (t == NITER - 1) ? 1 : 0);
    }
}

// round 10
// speedup vs baseline: 1.8137x; 1.8137x over previous
#include <cuda_runtime.h>
#include <cuda_fp16.h>

// ---------------- problem-size constants (fixed by the dataset) -------------
#define N_MAX   100032      // >= 100000 nodes
#define E_MAX   1600000
#define E_PAD   2001600     // E + 4*N padding headroom
#define D       50          // attrs
#define STRH    64          // padded row stride of fp16 buffers (64 halves = 128B)
#define NITER   30
#define SCAN_B  256

// ---------------- static device scratch (no allocations allowed) ------------
// Invariants at call entry (static zero on load; restored by each call):
//   g_deg == 0 (zeroed in k_iter t==0), g_meansum == 0 and g_ctr == 0
//   (zeroed in k_iter t==NITER-1). g_colsum zeroed inside k_scan_params.
__device__ int    g_deg[N_MAX];
__device__ int2   g_span[N_MAX];         // {start, end} per node (one 8B load)
__device__ int    g_rank[E_MAX];         // per-edge rank within its row
__device__ int    g_partial[512];
__device__ int    g_ctr;                 // grid-barrier arrival counter
__device__ int    g_csr[E_PAD];          // col*STRH (half offset); dummies -> row n
__device__ float  g_dinv[N_MAX];
__device__ unsigned char g_isknown[N_MAX];   // idempotent sets; never cleared
__device__ float  g_meansum[64];
__device__ float  g_mean[64];            // pads [50,64) stay 0 forever
__device__ float  g_alpha[64];
__device__ float  g_oma[64];
__device__ float  g_beta[64];
__device__ float  g_omb[64];
__device__ float  g_colsum[(NITER + 1) * 64];
__device__ int    g_need_colmean;        // set iff any alpha != 1
__device__ int    g_need_beta;
// zero-initialized; rows >= n are NEVER written, so dummy gathers read 0.
__device__ __half g_bufA[(size_t)N_MAX * STRH];
__device__ __half g_bufB[(size_t)N_MAX * STRH];

// ---------------- kernel 1: degrees(+rank) + isknown + mean partials --------
__global__ void k_deg_known_mean(const int* __restrict__ row,
                                 const int* __restrict__ km,
                                 const float* __restrict__ x, int E, int K) {
    int i = blockIdx.x * blockDim.x + threadIdx.x;
    if (i < E) g_rank[i] = atomicAdd(&g_deg[row[i]], 1);  // rank is free here
    if (i < K) g_isknown[km[i]] = 1;
    if (blockIdx.x < 100) {
        __shared__ float sm[64];
        if (threadIdx.x < 64) sm[threadIdx.x] = 0.f;
        __syncthreads();
        int lane = threadIdx.x & 31;
        int w  = (blockIdx.x * blockDim.x + threadIdx.x) >> 5;
        int nw = (100 * blockDim.x) >> 5;
        float2 acc = make_float2(0.f, 0.f);
        for (int k = w; k < K; k += nw) {
            int idx = km[k];
            if (lane < 25) {
                float2 vv = *(const float2*)(x + (size_t)idx * D + 2 * lane);
                acc.x += vv.x; acc.y += vv.y;
            }
        }
        if (lane < 25) {
            atomicAdd(&sm[2 * lane],     acc.x);
            atomicAdd(&sm[2 * lane + 1], acc.y);
        }
        __syncthreads();
        if (threadIdx.x < D) atomicAdd(&g_meansum[threadIdx.x], sm[threadIdx.x]);
    }
}

// ---------------- kernel 2: fused scan + spans + params (grid barrier) ------
// grid = ceil(n/256) = 391 blocks — fits in one resident wave; spin is safe.
__global__ void k_scan_params(int n, const float* __restrict__ eta,
                              const float* __restrict__ theta, int K) {
    __shared__ int s[SCAN_B];
    __shared__ int red[SCAN_B];
    __shared__ int fc, fb;
    int b = blockIdx.x, t = threadIdx.x;
    int i = b * SCAN_B + t;
    int nb = gridDim.x;

    if (i < (NITER + 1) * 64) g_colsum[i] = 0.f;

    int dg = (i < n) ? g_deg[i] : 0;
    if (i < n) g_dinv[i] = (dg > 0) ? rsqrtf((float)dg) : 0.f;
    int v = (dg + 3) & ~3;                      // padded length
    s[t] = v;
    __syncthreads();
    for (int d = 1; d < SCAN_B; d <<= 1) {
        int tmp = (t >= d) ? s[t - d] : 0;
        __syncthreads();
        s[t] += tmp;
        __syncthreads();
    }
    int excl = s[t] - v;
    if (t == SCAN_B - 1) {
        g_partial[b] = s[SCAN_B - 1];
        __threadfence();
    }
    __syncthreads();

    if (b == 0) {
        if (t == 0) { fc = 0; fb = 0; }
        __syncthreads();
        if (t < D) {
            g_mean[t] = g_meansum[t] / (float)K;
            float nf = (float)n;
            float a  = (nf - 1.f) / (theta[t] * nf + (nf - 1.f));
            float ia = 1.f / a;
            float bb = ia / (ia + eta[t]);
            g_alpha[t] = a;  g_oma[t] = 1.f - a;
            g_beta[t]  = bb; g_omb[t] = 1.f - bb;
            if (a  != 1.f) atomicExch(&fc, 1);
            if (bb != 1.f) atomicExch(&fb, 1);
        }
        __syncthreads();
        if (t == 0) { g_need_colmean = fc; g_need_beta = fb; }
    }

    // grid barrier: wait for all block totals
    if (t == 0) {
        atomicAdd(&g_ctr, 1);
        while (*(volatile int*)&g_ctr < nb) { }
    }
    __syncthreads();
    __threadfence();

    int local = 0;
    for (int j = t; j < b; j += SCAN_B) local += g_partial[j];
    red[t] = local;
    __syncthreads();
    for (int off = SCAN_B / 2; off > 0; off >>= 1) {
        if (t < off) red[t] += red[t + off];
        __syncthreads();
    }
    int base = red[0];

    if (i < n) {
        int s0 = base + excl;
        g_span[i] = make_int2(s0, s0 + v);
    }
}

// ---------------- kernel 3: fused scatter + pad-fill + y0 init --------------
// scatter is now ATOMIC-FREE: position = span[row].x + rank[e].
__global__ void k_build_init(const int* __restrict__ row, const int* __restrict__ col,
                             const float* __restrict__ x, int n, int E) {
    int tidg = blockIdx.x * blockDim.x + threadIdx.x;

    if (tidg < E) {
        int r = row[tidg];
        g_csr[g_span[r].x + g_rank[tidg]] = col[tidg] * STRH;
    }

    if (tidg < n) {
        int2 sp = g_span[tidg];
        int dummy = n * STRH;
        for (int j = sp.x + g_deg[tidg]; j < sp.y; ++j) g_csr[j] = dummy;
    }

    int gw   = tidg >> 5;
    int lane = threadIdx.x & 31;
    __shared__ float cs[64];
    int needc = g_need_colmean;
    if (needc) { if (threadIdx.x < 64) cs[threadIdx.x] = 0.f; __syncthreads(); }
    float2 v = make_float2(0.f, 0.f);
    if (gw < n) {
        if (lane < 25 && g_isknown[gw])
            v = *(const float2*)(x + (size_t)gw * D + 2 * lane);
        float2 m = ((const float2*)g_mean)[lane];
        v.x -= m.x; v.y -= m.y;
        float di = g_dinv[gw];
        if (lane < 25)
            *(__half2*)(g_bufA + (size_t)gw * STRH + 2 * lane) =
                __floats2half2_rn(di * v.x, di * v.y);
    }
    if (needc) {
        if (gw < n && lane < 25) {
            atomicAdd(&cs[2 * lane],     v.x);
            atomicAdd(&cs[2 * lane + 1], v.y);
        }
        __syncthreads();
        if (threadIdx.x < D) atomicAdd(&g_colsum[threadIdx.x], cs[threadIdx.x]);
    }
}

// ---------------- the hot loop: one propagation step (R6-proven body) -------
// warp-per-node; lanes 0..24 own a float2 of the 50 attrs. fp16 gathers,
// per-edge convert to fp32, fp32 accumulation. At the L1 wavefront floor.
__global__ __launch_bounds__(256) void k_iter(const float* __restrict__ x,
                                              float* __restrict__ fout,
                                              int n, float invn, int t, int last) {
    int tidg = blockIdx.x * blockDim.x + threadIdx.x;
    int gw   = tidg >> 5;
    int lane = threadIdx.x & 31;
    __shared__ float cs[64];
    const int needc = g_need_colmean;
    if (needc) { if (threadIdx.x < 64) cs[threadIdx.x] = 0.f; __syncthreads(); }

    // epilogue/prologue zeroing for the NEXT call (readers all in the past)
    if (t == 0 && tidg < n) g_deg[tidg] = 0;
    if (last) {
        if (tidg < 64) g_meansum[tidg] = 0.f;
        if (tidg == 0) g_ctr = 0;
    }

    const __half* in  = (t & 1) ? g_bufB : g_bufA;
    __half*       out = (t & 1) ? g_bufA : g_bufB;
    const float* cs_in  = g_colsum + t * 64;
    float*       cs_out = g_colsum + (t + 1) * 64;

    float2 v = make_float2(0.f, 0.f);
    if (gw < n) {
        int2 sp = g_span[gw];                     // one 8B uniform load
        int s = sp.x, e = sp.y;                   // 16B aligned, mult of 4
        const __half* inp = in + 2 * lane;
        float2 acc = make_float2(0.f, 0.f);
        int i = s;
        for (; i + 8 <= e; i += 8) {
            int4 c0 = *(const int4*)(g_csr + i);
            int4 c1 = *(const int4*)(g_csr + i + 4);
            float2 v0 = __half22float2(*(const __half2*)(inp + c0.x));
            float2 v1 = __half22float2(*(const __half2*)(inp + c0.y));
            float2 v2 = __half22float2(*(const __half2*)(inp + c0.z));
            float2 v3 = __half22float2(*(const __half2*)(inp + c0.w));
            float2 v4 = __half22float2(*(const __half2*)(inp + c1.x));
            float2 v5 = __half22float2(*(const __half2*)(inp + c1.y));
            float2 v6 = __half22float2(*(const __half2*)(inp + c1.z));
            float2 v7 = __half22float2(*(const __half2*)(inp + c1.w));
            acc.x += v0.x + v1.x + v2.x + v3.x + v4.x + v5.x + v6.x + v7.x;
            acc.y += v0.y + v1.y + v2.y + v3.y + v4.y + v5.y + v6.y + v7.y;
        }
        for (; i < e; i += 4) {
            int4 c0 = *(const int4*)(g_csr + i);
            float2 v0 = __half22float2(*(const __half2*)(inp + c0.x));
            float2 v1 = __half22float2(*(const __half2*)(inp + c0.y));
            float2 v2 = __half22float2(*(const __half2*)(inp + c0.z));
            float2 v3 = __half22float2(*(const __half2*)(inp + c0.w));
            acc.x += v0.x + v1.x + v2.x + v3.x;
            acc.y += v0.y + v1.y + v2.y + v3.y;
        }
        float di = g_dinv[gw];
        if (needc) {
            float2 a  = ((const float2*)g_alpha)[lane];
            float2 om = ((const float2*)g_oma)[lane];
            v.x = fmaf(a.x, di * acc.x, om.x * (cs_in[2 * lane]     * invn));
            v.y = fmaf(a.y, di * acc.y, om.y * (cs_in[2 * lane + 1] * invn));
        } else {
            v.x = di * acc.x;                     // alpha == 1 exactly
            v.y = di * acc.y;
        }
        if (g_need_beta && g_isknown[gw]) {
            float2 b  = ((const float2*)g_beta)[lane];
            float2 ob = ((const float2*)g_omb)[lane];
            float2 m  = ((const float2*)g_mean)[lane];
            float2 xv = make_float2(0.f, 0.f);
            if (lane < 25) xv = *(const float2*)(x + (size_t)gw * D + 2 * lane);
            v.x = b.x * v.x + ob.x * (xv.x - m.x);
            v.y = b.y * v.y + ob.y * (xv.y - m.y);
        }
        if (last) {
            float2 m = ((const float2*)g_mean)[lane];
            if (lane < 25)
                *(float2*)(fout + (size_t)gw * D + 2 * lane) =
                    make_float2(v.x + m.x, v.y + m.y);
        } else {
            if (lane < 25)
                *(__half2*)(out + (size_t)gw * STRH + 2 * lane) =
                    __floats2half2_rn(di * v.x, di * v.y);
        }
    }
    if (needc && !last) {
        if (gw < n && lane < 25) {
            atomicAdd(&cs[2 * lane],     v.x);
            atomicAdd(&cs[2 * lane + 1], v.y);
        }
        __syncthreads();
        if (threadIdx.x < D) atomicAdd(&cs_out[threadIdx.x], cs[threadIdx.x]);
    }
}

// ---------------- launcher ---------------------------------------------------
extern "C" void kernel_launch(void* const* d_in, const int* in_sizes, int n_in,
                              void* d_out, int out_size) {
    const float* x     = (const float*)d_in[0];
    const float* eta   = (const float*)d_in[1];
    const float* theta = (const float*)d_in[2];
    const int*   ei    = (const int*)d_in[3];
    const int*   km    = (const int*)d_in[4];

    int dd = in_sizes[1];              // 50
    int n  = in_sizes[0] / dd;         // 100000
    int E  = in_sizes[3] / 2;          // 1600000
    int K  = in_sizes[4];              // 50000
    const int* row = ei;
    const int* col = ei + E;

    const int TB = 256;
    int nbN = (n + TB - 1) / TB;       // 391 — one resident wave (safe to spin)
    int nbE = (E + TB - 1) / TB;
    int nbW = (n * 32 + TB - 1) / TB;  // warp-per-node grids (>= E threads)

    k_deg_known_mean<<<nbE, TB>>>(row, km, x, E, K);
    k_scan_params   <<<nbN, TB>>>(n, eta, theta, K);
    k_build_init    <<<nbW, TB>>>(row, col, x, n, E);

    float invn = 1.f / (float)n;
    for (int t = 0; t < NITER; ++t) {
        k_iter<<<nbW, TB>>>(x, (float*)d_out, n, invn, t, (t == NITER - 1) ? 1 : 0);
    }
}